// round 2
// baseline (speedup 1.0000x reference)
#include <cuda_runtime.h>
#include <cuda_bf16.h>
#include <cstdint>
#include <cstddef>

// Problem shapes (fixed by the dataset)
#define BB 8
#define SS 8192
#define DD 512
#define HH 512
#define OO 512
#define M_TOT (BB * SS)   // 65536

// Scratch (allocation-free: __device__ globals)
__device__ float g_hg[(size_t)M_TOT * (2 * HH)];  // 268 MB: [m, e] e in [0,1024)
__device__ float g_h [(size_t)M_TOT * HH];        // 134 MB: [m, h]

// ---------------------------------------------------------------------------
// SGEMM (NT): C[M,N] = A[M,K] * B[N,K]^T, fp32, 128x128x16 tiles, 8x8 microtile
// M % 128 == 0, N % 128 == 0, K % 16 == 0 (all hold here)
// ---------------------------------------------------------------------------
template <int BM, int BN, int BK, int TM, int TN>
__global__ void __launch_bounds__(256, 2)
sgemm_nt(const float* __restrict__ A,
         const float* __restrict__ Bw,
         float* __restrict__ C,
         int M, int N, int K)
{
    __shared__ float As[BK][BM];
    __shared__ float Bs[BK][BN];

    const int tid = threadIdx.x;
    const int m0  = blockIdx.y * BM;
    const int n0  = blockIdx.x * BN;

    const int tx = tid % (BN / TN);   // 0..15
    const int ty = tid / (BN / TN);   // 0..15

    float acc[TM][TN];
#pragma unroll
    for (int i = 0; i < TM; ++i)
#pragma unroll
        for (int j = 0; j < TN; ++j)
            acc[i][j] = 0.0f;

    // Tile-load mapping: BK=16 -> 4 float4 per row; 256 threads cover 64 rows/pass
    const int BK4  = BK / 4;               // 4
    const int lrow = tid / BK4;            // 0..63
    const int lcol = (tid % BK4) * 4;      // 0,4,8,12

    const float* Ab = A  + (size_t)m0 * K;
    const float* Bb = Bw + (size_t)n0 * K;

    for (int k0 = 0; k0 < K; k0 += BK) {
        // Load A tile (transposed into As[k][m])
#pragma unroll
        for (int p = 0; p < BM / 64; ++p) {
            const int r = lrow + p * 64;
            float4 v = *reinterpret_cast<const float4*>(Ab + (size_t)r * K + k0 + lcol);
            As[lcol + 0][r] = v.x;
            As[lcol + 1][r] = v.y;
            As[lcol + 2][r] = v.z;
            As[lcol + 3][r] = v.w;
        }
        // Load B tile (transposed into Bs[k][n])
#pragma unroll
        for (int p = 0; p < BN / 64; ++p) {
            const int r = lrow + p * 64;
            float4 v = *reinterpret_cast<const float4*>(Bb + (size_t)r * K + k0 + lcol);
            Bs[lcol + 0][r] = v.x;
            Bs[lcol + 1][r] = v.y;
            Bs[lcol + 2][r] = v.z;
            Bs[lcol + 3][r] = v.w;
        }
        __syncthreads();

#pragma unroll
        for (int kk = 0; kk < BK; ++kk) {
            float ra[TM], rb[TN];
#pragma unroll
            for (int i = 0; i < TM / 4; ++i) {
                float4 v = *reinterpret_cast<const float4*>(&As[kk][ty * TM + i * 4]);
                ra[i * 4 + 0] = v.x; ra[i * 4 + 1] = v.y;
                ra[i * 4 + 2] = v.z; ra[i * 4 + 3] = v.w;
            }
#pragma unroll
            for (int j = 0; j < TN / 4; ++j) {
                float4 v = *reinterpret_cast<const float4*>(&Bs[kk][tx * TN + j * 4]);
                rb[j * 4 + 0] = v.x; rb[j * 4 + 1] = v.y;
                rb[j * 4 + 2] = v.z; rb[j * 4 + 3] = v.w;
            }
#pragma unroll
            for (int i = 0; i < TM; ++i)
#pragma unroll
                for (int j = 0; j < TN; ++j)
                    acc[i][j] = fmaf(ra[i], rb[j], acc[i][j]);
        }
        __syncthreads();
    }

    // Epilogue: vectorized stores
#pragma unroll
    for (int i = 0; i < TM; ++i) {
        const size_t row = (size_t)(m0 + ty * TM + i) * N + n0 + tx * TN;
#pragma unroll
        for (int j = 0; j < TN / 4; ++j) {
            float4 v;
            v.x = acc[i][j * 4 + 0];
            v.y = acc[i][j * 4 + 1];
            v.z = acc[i][j * 4 + 2];
            v.w = acc[i][j * 4 + 3];
            *reinterpret_cast<float4*>(C + row + j * 4) = v;
        }
    }
}

// ---------------------------------------------------------------------------
// Scan: h_t = c_t * h_{t-1} + v_t over s, per (b, h) channel.
//   c = sigmoid(-g) = 1/(1+e^g)       (= exp(-softplus(g)))
//   v = sigmoid(g) * G(z),  G(z) = z>=0 ? z+0.5 : sigmoid(z)
// Reads hg directly (hidden at [m, h], gate at [m, h+512]); writes h and h_n.
// 4096 threads total: 128 blocks x 32.
// ---------------------------------------------------------------------------
__global__ void __launch_bounds__(32)
scan_kernel(const float* __restrict__ hg,
            float* __restrict__ h,
            float* __restrict__ hn_out)
{
    const int idx = blockIdx.x * blockDim.x + threadIdx.x;  // 0..4095
    const int b   = idx >> 9;        // / 512
    const int hh  = idx & 511;

    const float* base = hg + (size_t)b * SS * (2 * HH);
    float*       hb   = h  + (size_t)b * SS * HH;

    float hp = 0.0f;

    constexpr int U = 8;
#pragma unroll 1
    for (int s = 0; s < SS; s += U) {
        float z[U], g[U];
#pragma unroll
        for (int u = 0; u < U; ++u) {
            const size_t off = (size_t)(s + u) * (2 * HH);
            z[u] = base[off + hh];
            g[u] = base[off + HH + hh];
        }
#pragma unroll
        for (int u = 0; u < U; ++u) {
            const float eg  = __expf(g[u]);
            const float inv = __frcp_rn(1.0f + eg);
            const float c   = inv;            // sigmoid(-g)
            const float smg = eg * inv;       // sigmoid(g)
            float G;
            if (z[u] >= 0.0f) {
                G = z[u] + 0.5f;
            } else {
                const float ez = __expf(z[u]);
                G = ez * __frcp_rn(1.0f + ez); // sigmoid(z)
            }
            hp = fmaf(c, hp, smg * G);
            hb[(size_t)(s + u) * HH + hh] = hp;
        }
    }
    hn_out[idx] = hp;  // h_n[b, h]
}

// ---------------------------------------------------------------------------
// Launch
// ---------------------------------------------------------------------------
extern "C" void kernel_launch(void* const* d_in, const int* in_sizes, int n_in,
                              void* d_out, int out_size)
{
    const float* x     = (const float*)d_in[0];
    // d_in[1] = is_init (unused by the reference math)
    const float* W_hg  = (const float*)d_in[2];
    const float* W_out = (const float*)d_in[3];
    float* out = (float*)d_out;

    float *hg_ptr = nullptr, *h_ptr = nullptr;
    cudaGetSymbolAddress((void**)&hg_ptr, g_hg);
    cudaGetSymbolAddress((void**)&h_ptr,  g_h);

    // GEMM1: hg = x @ W_hg^T   (M=65536, N=1024, K=512)
    {
        dim3 grid((2 * HH) / 128, M_TOT / 128);
        sgemm_nt<128, 128, 16, 8, 8><<<grid, 256>>>(x, W_hg, hg_ptr,
                                                    M_TOT, 2 * HH, DD);
    }

    // Scan: h, h_n
    {
        float* hn = out + (size_t)M_TOT * OO;
        scan_kernel<<<128, 32>>>(hg_ptr, h_ptr, hn);
    }

    // GEMM2: out = h @ W_out^T  (M=65536, N=512, K=512)
    {
        dim3 grid(OO / 128, M_TOT / 128);
        sgemm_nt<128, 128, 16, 8, 8><<<grid, 256>>>(h_ptr, W_out, out,
                                                    M_TOT, OO, HH);
    }
}

// round 4
// speedup vs baseline: 1.7862x; 1.7862x over previous
#include <cuda_runtime.h>
#include <cuda_bf16.h>
#include <cstdint>
#include <cstddef>

// Problem shapes (fixed)
#define BB 8
#define SS 8192
#define DD 512
#define HH 512
#define OO 512
#define M_TOT (BB * SS)   // 65536
#define K3   1536         // 3 * 512 (bf16 split-3 expanded K)

// ---------------------------------------------------------------------------
// Scratch (__device__ globals — allocation-free)
// ---------------------------------------------------------------------------
__device__ float         g_hg[(size_t)M_TOT * 1024];   // 268 MB fp32 [m, 1024]
__device__ __nv_bfloat16 g_x3[(size_t)M_TOT * K3];     // 201 MB [m, 1536] = [hi|lo|hi]
__device__ __nv_bfloat16 g_h3[(size_t)M_TOT * K3];     // 201 MB [m, 1536] = [hi|lo|hi]
__device__ __nv_bfloat16 g_w1[(size_t)1024 * K3];      // 3 MB  [n, 1536] = [hi|hi|lo]
__device__ __nv_bfloat16 g_w2[(size_t)512  * K3];      // 1.5MB [n, 1536] = [hi|hi|lo]

// ---------------------------------------------------------------------------
// Helpers
// ---------------------------------------------------------------------------
__device__ __forceinline__ uint32_t smem_u32(const void* p) {
    uint32_t a;
    asm("{ .reg .u64 t; cvta.to.shared.u64 t, %1; cvt.u32.u64 %0, t; }" : "=r"(a) : "l"(p));
    return a;
}

__device__ __forceinline__ void cp_async16(uint32_t sdst, const void* gsrc) {
    asm volatile("cp.async.cg.shared.global [%0], [%1], 16;" :: "r"(sdst), "l"(gsrc) : "memory");
}

__device__ __forceinline__ void ldsm4(uint32_t* r, uint32_t addr) {
    asm volatile("ldmatrix.sync.aligned.m8n8.x4.shared.b16 {%0,%1,%2,%3}, [%4];"
                 : "=r"(r[0]), "=r"(r[1]), "=r"(r[2]), "=r"(r[3]) : "r"(addr));
}

__device__ __forceinline__ void mma16816(float* c, const uint32_t* a, const uint32_t* b) {
    asm volatile("mma.sync.aligned.m16n8k16.row.col.f32.bf16.bf16.f32 "
                 "{%0,%1,%2,%3}, {%4,%5,%6,%7}, {%8,%9}, {%0,%1,%2,%3};"
                 : "+f"(c[0]), "+f"(c[1]), "+f"(c[2]), "+f"(c[3])
                 : "r"(a[0]), "r"(a[1]), "r"(a[2]), "r"(a[3]), "r"(b[0]), "r"(b[1]));
}

__device__ __forceinline__ uint32_t swz(uint32_t off) {  // SW128: bits[6:4] ^= bits[9:7]
    return off ^ ((off >> 3) & 0x70);
}

// ---------------------------------------------------------------------------
// bf16 HMMA GEMM (NT): C[M, Ntot] = A3[M, K3] * B3[Ntot, K3]^T, fp32 accum
// Tile 128(M) x 128(N) x 64(K), 8 warps (2M x 4N), warp tile 64x32
// 3-stage cp.async pipeline, SW128 swizzled smem, ldmatrix.x4 operands
// ---------------------------------------------------------------------------
#define NCH      (K3 / 64)          // 24 K-chunks
#define STAGE_B  32768              // 16KB A + 16KB B
#define NSTAGE   3
#define SMEM_DYN (NSTAGE * STAGE_B + 1024)

__global__ void __launch_bounds__(256)
gemm_bf16_mma(const __nv_bfloat16* __restrict__ A,
              const __nv_bfloat16* __restrict__ Bw,
              float* __restrict__ C,
              int Ntot)
{
    extern __shared__ char dyn_smem[];
    const uint32_t smem_al = (smem_u32(dyn_smem) + 1023u) & ~1023u;

    const int tid  = threadIdx.x;
    const int lane = tid & 31;
    const int wid  = tid >> 5;
    const int wm   = wid & 1;    // 0..1  (M)
    const int wn   = wid >> 1;   // 0..3  (N)

    const int m0 = blockIdx.y * 128;
    const int n0 = blockIdx.x * 128;

    // Global load mapping: 2048 x 16B chunks per stage over 256 threads (8 each)
    // idx < 1024 -> A rows, else B rows. r = chunk row, c = 16B column (0..7)
    const char* Ab = (const char*)(A  + (size_t)m0 * K3);
    const char* Bb = (const char*)(Bw + (size_t)n0 * K3);

    // ldmatrix per-lane byte bases (within a stage's A / B tile, 128B rows)
    const uint32_t aBase = (uint32_t)((wm * 64 + ((lane >> 3) & 1) * 8 + (lane & 7)) * 128
                                      + (lane >> 4) * 16);
    const uint32_t bBase = (uint32_t)((wn * 32 + (lane >> 4) * 8 + (lane & 7)) * 128
                                      + ((lane >> 3) & 1) * 16);

    float acc[4][4][4];
#pragma unroll
    for (int i = 0; i < 4; ++i)
#pragma unroll
        for (int j = 0; j < 4; ++j)
#pragma unroll
            for (int k = 0; k < 4; ++k) acc[i][j][k] = 0.0f;

    auto load_stage = [&](int i) {
        const uint32_t base = smem_al + (i % NSTAGE) * STAGE_B;
        const size_t kofs = (size_t)i * 128;  // bytes into the K3 row
#pragma unroll
        for (int p = 0; p < 8; ++p) {
            const int idx = tid + p * 256;
            const int r = (idx >> 3) & 127;
            const int c = idx & 7;
            const uint32_t so = swz((uint32_t)(r << 7) + (uint32_t)(c << 4));
            if (idx < 1024)
                cp_async16(base + so,         Ab + (size_t)r * (K3 * 2) + kofs + c * 16);
            else
                cp_async16(base + 16384 + so, Bb + (size_t)r * (K3 * 2) + kofs + c * 16);
        }
        asm volatile("cp.async.commit_group;" ::: "memory");
    };

    load_stage(0);
    load_stage(1);

    for (int i = 0; i < NCH; ++i) {
        if (i + 1 < NCH) asm volatile("cp.async.wait_group 1;" ::: "memory");
        else             asm volatile("cp.async.wait_group 0;" ::: "memory");
        __syncthreads();
        if (i + 2 < NCH) load_stage(i + 2);

        const uint32_t sA = smem_al + (i % NSTAGE) * STAGE_B;
        const uint32_t sB = sA + 16384;

#pragma unroll
        for (int ks = 0; ks < 4; ++ks) {
            uint32_t afr[4][4], bfr[2][4];
#pragma unroll
            for (int mt = 0; mt < 4; ++mt)
                ldsm4(afr[mt], sA + swz(aBase + (uint32_t)(mt * 2048 + ks * 32)));
#pragma unroll
            for (int q = 0; q < 2; ++q)
                ldsm4(bfr[q], sB + swz(bBase + (uint32_t)(q * 2048 + ks * 32)));
#pragma unroll
            for (int mt = 0; mt < 4; ++mt)
#pragma unroll
                for (int nt = 0; nt < 4; ++nt) {
                    uint32_t b2[2] = { bfr[nt >> 1][(nt & 1) * 2 + 0],
                                       bfr[nt >> 1][(nt & 1) * 2 + 1] };
                    mma16816(acc[mt][nt], afr[mt], b2);
                }
        }
        __syncthreads();
    }

    // Epilogue: fp32 stores (thread t of m16n8 frag: rows t/4, t/4+8; cols (t%4)*2,+1)
    const int er = lane >> 2;
    const int ec = (lane & 3) * 2;
#pragma unroll
    for (int mt = 0; mt < 4; ++mt) {
#pragma unroll
        for (int nt = 0; nt < 4; ++nt) {
            float* p0 = C + (size_t)(m0 + wm * 64 + mt * 16 + er) * Ntot
                          + n0 + wn * 32 + nt * 8 + ec;
            float* p1 = p0 + (size_t)8 * Ntot;
            *reinterpret_cast<float2*>(p0) = make_float2(acc[mt][nt][0], acc[mt][nt][1]);
            *reinterpret_cast<float2*>(p1) = make_float2(acc[mt][nt][2], acc[mt][nt][3]);
        }
    }
}

// ---------------------------------------------------------------------------
// fp32 -> bf16 split-3 expansion.
// wside=0 (A side): [hi | lo | hi];  wside=1 (B side): [hi | hi | lo]
// ---------------------------------------------------------------------------
__global__ void __launch_bounds__(256)
split3_kernel(const float* __restrict__ in, __nv_bfloat16* __restrict__ out,
              size_t total, int wside)
{
    for (size_t i = (size_t)blockIdx.x * blockDim.x + threadIdx.x; i < total;
         i += (size_t)gridDim.x * blockDim.x) {
        const size_t row = i >> 9;
        const int k = (int)(i & 511);
        const float a = in[i];
        const __nv_bfloat16 hi = __float2bfloat16(a);
        const __nv_bfloat16 lo = __float2bfloat16(a - __bfloat162float(hi));
        __nv_bfloat16* o = out + row * K3;
        if (wside) { o[k] = hi; o[512 + k] = hi; o[1024 + k] = lo; }
        else       { o[k] = hi; o[512 + k] = lo; o[1024 + k] = hi; }
    }
}

// ---------------------------------------------------------------------------
// Scan: h_t = c_t * h_{t-1} + v_t per (b, h); writes split-3 bf16 h3 + fp32 h_n
// ---------------------------------------------------------------------------
__global__ void __launch_bounds__(32)
scan_kernel(const float* __restrict__ hg,
            __nv_bfloat16* __restrict__ h3,
            float* __restrict__ hn_out)
{
    const int idx = blockIdx.x * blockDim.x + threadIdx.x;  // 0..4095
    const int b = idx >> 9;
    const int hh = idx & 511;

    const float* base = hg + (size_t)b * SS * 1024;
    __nv_bfloat16* h3b = h3 + (size_t)b * SS * K3;

    float hp = 0.0f;
    constexpr int U = 16;
#pragma unroll 1
    for (int s = 0; s < SS; s += U) {
        float z[U], g[U];
#pragma unroll
        for (int u = 0; u < U; ++u) {
            const size_t off = (size_t)(s + u) * 1024;
            z[u] = base[off + hh];
            g[u] = base[off + 512 + hh];
        }
#pragma unroll
        for (int u = 0; u < U; ++u) {
            const float eg  = __expf(g[u]);
            const float inv = __frcp_rn(1.0f + eg);
            const float c   = inv;        // sigmoid(-g)
            const float smg = eg * inv;   // sigmoid(g)
            float G;
            if (z[u] >= 0.0f) {
                G = z[u] + 0.5f;
            } else {
                const float ez = __expf(z[u]);
                G = ez * __frcp_rn(1.0f + ez);
            }
            hp = fmaf(c, hp, smg * G);
            const __nv_bfloat16 hi = __float2bfloat16(hp);
            const __nv_bfloat16 lo = __float2bfloat16(hp - __bfloat162float(hi));
            __nv_bfloat16* o = h3b + (size_t)(s + u) * K3;
            o[hh] = hi; o[512 + hh] = lo; o[1024 + hh] = hi;
        }
    }
    hn_out[idx] = hp;
}

// ---------------------------------------------------------------------------
// Launch
// ---------------------------------------------------------------------------
extern "C" void kernel_launch(void* const* d_in, const int* in_sizes, int n_in,
                              void* d_out, int out_size)
{
    const float* x     = (const float*)d_in[0];
    const float* W_hg  = (const float*)d_in[2];
    const float* W_out = (const float*)d_in[3];
    float* out = (float*)d_out;

    float *hg_ptr = nullptr;
    __nv_bfloat16 *x3 = nullptr, *h3 = nullptr, *w1 = nullptr, *w2 = nullptr;
    cudaGetSymbolAddress((void**)&hg_ptr, g_hg);
    cudaGetSymbolAddress((void**)&x3, g_x3);
    cudaGetSymbolAddress((void**)&h3, g_h3);
    cudaGetSymbolAddress((void**)&w1, g_w1);
    cudaGetSymbolAddress((void**)&w2, g_w2);
    float* hn = out + (size_t)M_TOT * OO;

    cudaFuncSetAttribute(gemm_bf16_mma, cudaFuncAttributeMaxDynamicSharedMemorySize, SMEM_DYN);

    // Split-3 conversions
    split3_kernel<<<2048, 256>>>(x, x3, (size_t)M_TOT * 512, 0);
    split3_kernel<<<256, 256>>>(W_hg, w1, (size_t)1024 * 512, 1);
    split3_kernel<<<256, 256>>>(W_out, w2, (size_t)512 * 512, 1);

    // GEMM1: hg = x @ W_hg^T  (M=65536, N=1024, K'=1536)
    {
        dim3 grid(1024 / 128, M_TOT / 128);
        gemm_bf16_mma<<<grid, 256, SMEM_DYN>>>(x3, w1, hg_ptr, 1024);
    }

    // Scan -> h3 (split-3) + h_n
    scan_kernel<<<128, 32>>>(hg_ptr, h3, hn);

    // GEMM2: out = h @ W_out^T  (M=65536, N=512, K'=1536)
    {
        dim3 grid(512 / 128, M_TOT / 128);
        gemm_bf16_mma<<<grid, 256, SMEM_DYN>>>(h3, w2, out, 512);
    }
}

// round 5
// speedup vs baseline: 4.3072x; 2.4114x over previous
#include <cuda_runtime.h>
#include <cuda_bf16.h>
#include <cstdint>
#include <cstddef>

// Problem shapes (fixed)
#define BB 8
#define SS 8192
#define DD 512
#define HH 512
#define OO 512
#define M_TOT (BB * SS)   // 65536
#define K3   1536         // 3 * 512 (bf16 split-3 expanded K)
#define NCHK 32           // scan chunks per sequence
#define CLEN (SS / NCHK)  // 256
#define NCHAN (BB * HH)   // 4096
#define NCC  (NCHAN * NCHK)  // 131072 chunk-channels

// ---------------------------------------------------------------------------
// Scratch (__device__ globals — allocation-free)
// ---------------------------------------------------------------------------
__device__ float         g_hg[(size_t)M_TOT * 1024];   // 268 MB fp32 [m, 1024]
__device__ __nv_bfloat16 g_x3[(size_t)M_TOT * K3];     // 201 MB [m,1536] = [hi|lo|hi]
__device__ __nv_bfloat16 g_h3[(size_t)M_TOT * K3];     // 201 MB [m,1536] = [hi|lo|hi]
__device__ __nv_bfloat16 g_w1[(size_t)1024 * K3];      // [n,1536] = [hi|hi|lo]
__device__ __nv_bfloat16 g_w2[(size_t)512  * K3];      // [n,1536] = [hi|hi|lo]
__device__ float g_chA[NCC];      // per-chunk coeff product
__device__ float g_chB[NCC];      // per-chunk local scan value
__device__ float g_hstart[NCC];   // per-chunk starting state

// ---------------------------------------------------------------------------
// Helpers
// ---------------------------------------------------------------------------
__device__ __forceinline__ uint32_t smem_u32(const void* p) {
    uint32_t a;
    asm("{ .reg .u64 t; cvta.to.shared.u64 t, %1; cvt.u32.u64 %0, t; }" : "=r"(a) : "l"(p));
    return a;
}
__device__ __forceinline__ void cp_async16(uint32_t sdst, const void* gsrc) {
    asm volatile("cp.async.cg.shared.global [%0], [%1], 16;" :: "r"(sdst), "l"(gsrc) : "memory");
}
__device__ __forceinline__ void ldsm4(uint32_t* r, uint32_t addr) {
    asm volatile("ldmatrix.sync.aligned.m8n8.x4.shared.b16 {%0,%1,%2,%3}, [%4];"
                 : "=r"(r[0]), "=r"(r[1]), "=r"(r[2]), "=r"(r[3]) : "r"(addr));
}
__device__ __forceinline__ void mma16816(float* c, const uint32_t* a, const uint32_t* b) {
    asm volatile("mma.sync.aligned.m16n8k16.row.col.f32.bf16.bf16.f32 "
                 "{%0,%1,%2,%3}, {%4,%5,%6,%7}, {%8,%9}, {%0,%1,%2,%3};"
                 : "+f"(c[0]), "+f"(c[1]), "+f"(c[2]), "+f"(c[3])
                 : "r"(a[0]), "r"(a[1]), "r"(a[2]), "r"(a[3]), "r"(b[0]), "r"(b[1]));
}
__device__ __forceinline__ uint32_t swz(uint32_t off) {  // SW128
    return off ^ ((off >> 3) & 0x70);
}
__device__ __forceinline__ float frcp(float x) {  // MUFU RCP approx
    float r;
    asm("rcp.approx.f32 %0, %1;" : "=f"(r) : "f"(x));
    return r;
}

// Gate math: c = sigmoid(-g), v = sigmoid(g) * G(z)
__device__ __forceinline__ void gate_cv(float z, float g, float& c, float& v) {
    const float eg  = __expf(g);
    const float inv = frcp(1.0f + eg);
    c = inv;
    const float smg = eg * inv;
    float G;
    if (z >= 0.0f) G = z + 0.5f;
    else {
        const float ez = __expf(z);
        G = ez * frcp(1.0f + ez);
    }
    v = smg * G;
}

// ---------------------------------------------------------------------------
// bf16 HMMA GEMM (NT): C[M,Ntot] = A3[M,K3] * B3[Ntot,K3]^T, fp32 accum
// 128x128x64 tile, 8 warps (2Mx4N), 3-stage cp.async, SW128 smem
// ---------------------------------------------------------------------------
#define NCHG     (K3 / 64)
#define STAGE_B  32768
#define NSTAGE   3
#define SMEM_DYN (NSTAGE * STAGE_B + 1024)

__global__ void __launch_bounds__(256)
gemm_bf16_mma(const __nv_bfloat16* __restrict__ A,
              const __nv_bfloat16* __restrict__ Bw,
              float* __restrict__ C,
              int Ntot)
{
    extern __shared__ char dyn_smem[];
    const uint32_t smem_al = (smem_u32(dyn_smem) + 1023u) & ~1023u;

    const int tid  = threadIdx.x;
    const int lane = tid & 31;
    const int wid  = tid >> 5;
    const int wm   = wid & 1;
    const int wn   = wid >> 1;

    const int m0 = blockIdx.y * 128;
    const int n0 = blockIdx.x * 128;

    const char* Ab = (const char*)(A  + (size_t)m0 * K3);
    const char* Bb = (const char*)(Bw + (size_t)n0 * K3);

    const uint32_t aBase = (uint32_t)((wm * 64 + ((lane >> 3) & 1) * 8 + (lane & 7)) * 128
                                      + (lane >> 4) * 16);
    const uint32_t bBase = (uint32_t)((wn * 32 + (lane >> 4) * 8 + (lane & 7)) * 128
                                      + ((lane >> 3) & 1) * 16);

    float acc[4][4][4];
#pragma unroll
    for (int i = 0; i < 4; ++i)
#pragma unroll
        for (int j = 0; j < 4; ++j)
#pragma unroll
            for (int k = 0; k < 4; ++k) acc[i][j][k] = 0.0f;

    auto load_stage = [&](int i) {
        const uint32_t base = smem_al + (i % NSTAGE) * STAGE_B;
        const size_t kofs = (size_t)i * 128;
#pragma unroll
        for (int p = 0; p < 8; ++p) {
            const int idx = tid + p * 256;
            const int r = (idx >> 3) & 127;
            const int c = idx & 7;
            const uint32_t so = swz((uint32_t)(r << 7) + (uint32_t)(c << 4));
            if (idx < 1024)
                cp_async16(base + so,         Ab + (size_t)r * (K3 * 2) + kofs + c * 16);
            else
                cp_async16(base + 16384 + so, Bb + (size_t)r * (K3 * 2) + kofs + c * 16);
        }
        asm volatile("cp.async.commit_group;" ::: "memory");
    };

    load_stage(0);
    load_stage(1);

    for (int i = 0; i < NCHG; ++i) {
        if (i + 1 < NCHG) asm volatile("cp.async.wait_group 1;" ::: "memory");
        else              asm volatile("cp.async.wait_group 0;" ::: "memory");
        __syncthreads();
        if (i + 2 < NCHG) load_stage(i + 2);

        const uint32_t sA = smem_al + (i % NSTAGE) * STAGE_B;
        const uint32_t sB = sA + 16384;

#pragma unroll
        for (int ks = 0; ks < 4; ++ks) {
            uint32_t afr[4][4], bfr[2][4];
#pragma unroll
            for (int mt = 0; mt < 4; ++mt)
                ldsm4(afr[mt], sA + swz(aBase + (uint32_t)(mt * 2048 + ks * 32)));
#pragma unroll
            for (int q = 0; q < 2; ++q)
                ldsm4(bfr[q], sB + swz(bBase + (uint32_t)(q * 2048 + ks * 32)));
#pragma unroll
            for (int mt = 0; mt < 4; ++mt)
#pragma unroll
                for (int nt = 0; nt < 4; ++nt) {
                    uint32_t b2[2] = { bfr[nt >> 1][(nt & 1) * 2 + 0],
                                       bfr[nt >> 1][(nt & 1) * 2 + 1] };
                    mma16816(acc[mt][nt], afr[mt], b2);
                }
        }
        __syncthreads();
    }

    const int er = lane >> 2;
    const int ec = (lane & 3) * 2;
#pragma unroll
    for (int mt = 0; mt < 4; ++mt) {
#pragma unroll
        for (int nt = 0; nt < 4; ++nt) {
            float* p0 = C + (size_t)(m0 + wm * 64 + mt * 16 + er) * Ntot
                          + n0 + wn * 32 + nt * 8 + ec;
            float* p1 = p0 + (size_t)8 * Ntot;
            *reinterpret_cast<float2*>(p0) = make_float2(acc[mt][nt][0], acc[mt][nt][1]);
            *reinterpret_cast<float2*>(p1) = make_float2(acc[mt][nt][2], acc[mt][nt][3]);
        }
    }
}

// ---------------------------------------------------------------------------
// fp32 -> bf16 split-3 expansion
// ---------------------------------------------------------------------------
__global__ void __launch_bounds__(256)
split3_kernel(const float* __restrict__ in, __nv_bfloat16* __restrict__ out,
              size_t total, int wside)
{
    for (size_t i = (size_t)blockIdx.x * blockDim.x + threadIdx.x; i < total;
         i += (size_t)gridDim.x * blockDim.x) {
        const size_t row = i >> 9;
        const int k = (int)(i & 511);
        const float a = in[i];
        const __nv_bfloat16 hi = __float2bfloat16(a);
        const __nv_bfloat16 lo = __float2bfloat16(a - __bfloat162float(hi));
        __nv_bfloat16* o = out + row * K3;
        if (wside) { o[k] = hi; o[512 + k] = hi; o[1024 + k] = lo; }
        else       { o[k] = hi; o[512 + k] = lo; o[1024 + k] = hi; }
    }
}

// ---------------------------------------------------------------------------
// Scan pass 1: per (b, chunk, h) compute A = prod c, B = local scan from 0
// idx = (b*NCHK + chunk)*512 + h  (h fastest -> coalesced)
// ---------------------------------------------------------------------------
__global__ void __launch_bounds__(256)
scan_pass1(const float* __restrict__ hg,
           float* __restrict__ chA, float* __restrict__ chB)
{
    const int idx = blockIdx.x * blockDim.x + threadIdx.x;  // < NCC
    const int hh = idx & 511;
    const int bc = idx >> 9;
    const int b  = bc >> 5;
    const int ck = bc & (NCHK - 1);

    const float* base = hg + ((size_t)b * SS + (size_t)ck * CLEN) * 1024;

    float A = 1.0f, h = 0.0f;
    constexpr int U = 8;
#pragma unroll 1
    for (int s = 0; s < CLEN; s += U) {
        float z[U], g[U];
#pragma unroll
        for (int u = 0; u < U; ++u) {
            const size_t off = (size_t)(s + u) * 1024;
            z[u] = base[off + hh];
            g[u] = base[off + 512 + hh];
        }
#pragma unroll
        for (int u = 0; u < U; ++u) {
            float c, v;
            gate_cv(z[u], g[u], c, v);
            h = fmaf(c, h, v);
            A *= c;
        }
    }
    chA[idx] = A;
    chB[idx] = h;
}

// ---------------------------------------------------------------------------
// Scan pass 2: per (b, h) combine chunk summaries -> h_start per chunk + h_n
// ---------------------------------------------------------------------------
__global__ void __launch_bounds__(256)
scan_pass2(const float* __restrict__ chA, const float* __restrict__ chB,
           float* __restrict__ hstart, float* __restrict__ hn_out)
{
    const int idx = blockIdx.x * blockDim.x + threadIdx.x;  // < NCHAN
    const int hh = idx & 511;
    const int b  = idx >> 9;

    float h = 0.0f;
#pragma unroll
    for (int ck = 0; ck < NCHK; ++ck) {
        const int cidx = (b * NCHK + ck) * 512 + hh;
        hstart[cidx] = h;
        h = fmaf(chA[cidx], h, chB[cidx]);
    }
    hn_out[idx] = h;
}

// ---------------------------------------------------------------------------
// Scan pass 3: replay each chunk from exact h_start, write split-3 bf16 h3
// ---------------------------------------------------------------------------
__global__ void __launch_bounds__(256)
scan_pass3(const float* __restrict__ hg, const float* __restrict__ hstart,
           __nv_bfloat16* __restrict__ h3)
{
    const int idx = blockIdx.x * blockDim.x + threadIdx.x;  // < NCC
    const int hh = idx & 511;
    const int bc = idx >> 9;
    const int b  = bc >> 5;
    const int ck = bc & (NCHK - 1);

    const float* base = hg + ((size_t)b * SS + (size_t)ck * CLEN) * 1024;
    __nv_bfloat16* h3b = g_h3 + ((size_t)b * SS + (size_t)ck * CLEN) * K3;
    (void)h3;

    float h = hstart[idx];
    constexpr int U = 8;
#pragma unroll 1
    for (int s = 0; s < CLEN; s += U) {
        float z[U], g[U];
#pragma unroll
        for (int u = 0; u < U; ++u) {
            const size_t off = (size_t)(s + u) * 1024;
            z[u] = base[off + hh];
            g[u] = base[off + 512 + hh];
        }
#pragma unroll
        for (int u = 0; u < U; ++u) {
            float c, v;
            gate_cv(z[u], g[u], c, v);
            h = fmaf(c, h, v);
            const __nv_bfloat16 hi = __float2bfloat16(h);
            const __nv_bfloat16 lo = __float2bfloat16(h - __bfloat162float(hi));
            __nv_bfloat16* o = h3b + (size_t)(s + u) * K3;
            o[hh] = hi; o[512 + hh] = lo; o[1024 + hh] = hi;
        }
    }
}

// ---------------------------------------------------------------------------
// Launch
// ---------------------------------------------------------------------------
extern "C" void kernel_launch(void* const* d_in, const int* in_sizes, int n_in,
                              void* d_out, int out_size)
{
    const float* x     = (const float*)d_in[0];
    const float* W_hg  = (const float*)d_in[2];
    const float* W_out = (const float*)d_in[3];
    float* out = (float*)d_out;

    float *hg_ptr, *chA, *chB, *hstart;
    __nv_bfloat16 *x3, *h3, *w1, *w2;
    cudaGetSymbolAddress((void**)&hg_ptr, g_hg);
    cudaGetSymbolAddress((void**)&x3, g_x3);
    cudaGetSymbolAddress((void**)&h3, g_h3);
    cudaGetSymbolAddress((void**)&w1, g_w1);
    cudaGetSymbolAddress((void**)&w2, g_w2);
    cudaGetSymbolAddress((void**)&chA, g_chA);
    cudaGetSymbolAddress((void**)&chB, g_chB);
    cudaGetSymbolAddress((void**)&hstart, g_hstart);
    float* hn = out + (size_t)M_TOT * OO;

    cudaFuncSetAttribute(gemm_bf16_mma, cudaFuncAttributeMaxDynamicSharedMemorySize, SMEM_DYN);

    // Split-3 conversions
    split3_kernel<<<2048, 256>>>(x, x3, (size_t)M_TOT * 512, 0);
    split3_kernel<<<256, 256>>>(W_hg, w1, (size_t)1024 * 512, 1);
    split3_kernel<<<256, 256>>>(W_out, w2, (size_t)512 * 512, 1);

    // GEMM1: hg = x @ W_hg^T  (M=65536, N=1024, K'=1536)
    {
        dim3 grid(1024 / 128, M_TOT / 128);
        gemm_bf16_mma<<<grid, 256, SMEM_DYN>>>(x3, w1, hg_ptr, 1024);
    }

    // Parallel scan
    scan_pass1<<<NCC / 256, 256>>>(hg_ptr, chA, chB);
    scan_pass2<<<NCHAN / 256, 256>>>(chA, chB, hstart, hn);
    scan_pass3<<<NCC / 256, 256>>>(hg_ptr, hstart, h3);

    // GEMM2: out = h @ W_out^T  (M=65536, N=512, K'=1536)
    {
        dim3 grid(512 / 128, M_TOT / 128);
        gemm_bf16_mma<<<grid, 256, SMEM_DYN>>>(h3, w2, out, 512);
    }
}

// round 6
// speedup vs baseline: 9.0112x; 2.0921x over previous
#include <cuda_runtime.h>
#include <cuda_fp16.h>
#include <cstdint>
#include <cstddef>

// Problem shapes (fixed)
#define BB 8
#define SS 8192
#define DD 512
#define HH 512
#define OO 512
#define M_TOT (BB * SS)   // 65536
#define NCHK 32           // scan chunks per sequence
#define CLEN (SS / NCHK)  // 256
#define NCHAN (BB * HH)   // 4096
#define NCC  (NCHAN * NCHK)  // 131072

// ---------------------------------------------------------------------------
// Scratch (__device__ globals — allocation-free)
// ---------------------------------------------------------------------------
__device__ float  g_hg[(size_t)M_TOT * 1024];   // 268 MB fp32 [m, 1024]
__device__ __half g_xh[(size_t)M_TOT * DD];     // 67 MB fp16 [m, 512]
__device__ __half g_hh[(size_t)M_TOT * HH];     // 67 MB fp16 [m, 512]
__device__ __half g_w1h[(size_t)1024 * DD];     // fp16 [n, 512]
__device__ __half g_w2h[(size_t)512  * HH];     // fp16 [n, 512]
__device__ float g_chA[NCC];
__device__ float g_chB[NCC];
__device__ float g_hstart[NCC];

// ---------------------------------------------------------------------------
// Helpers
// ---------------------------------------------------------------------------
__device__ __forceinline__ uint32_t smem_u32(const void* p) {
    uint32_t a;
    asm("{ .reg .u64 t; cvta.to.shared.u64 t, %1; cvt.u32.u64 %0, t; }" : "=r"(a) : "l"(p));
    return a;
}
__device__ __forceinline__ void cp_async16(uint32_t sdst, const void* gsrc) {
    asm volatile("cp.async.cg.shared.global [%0], [%1], 16;" :: "r"(sdst), "l"(gsrc) : "memory");
}
__device__ __forceinline__ void ldsm4(uint32_t* r, uint32_t addr) {
    asm volatile("ldmatrix.sync.aligned.m8n8.x4.shared.b16 {%0,%1,%2,%3}, [%4];"
                 : "=r"(r[0]), "=r"(r[1]), "=r"(r[2]), "=r"(r[3]) : "r"(addr));
}
__device__ __forceinline__ void mma16816(float* c, const uint32_t* a, const uint32_t* b) {
    asm volatile("mma.sync.aligned.m16n8k16.row.col.f32.f16.f16.f32 "
                 "{%0,%1,%2,%3}, {%4,%5,%6,%7}, {%8,%9}, {%0,%1,%2,%3};"
                 : "+f"(c[0]), "+f"(c[1]), "+f"(c[2]), "+f"(c[3])
                 : "r"(a[0]), "r"(a[1]), "r"(a[2]), "r"(a[3]), "r"(b[0]), "r"(b[1]));
}
__device__ __forceinline__ uint32_t swz(uint32_t off) {  // SW128
    return off ^ ((off >> 3) & 0x70);
}
__device__ __forceinline__ float frcp(float x) {
    float r;
    asm("rcp.approx.f32 %0, %1;" : "=f"(r) : "f"(x));
    return r;
}

// Gate math: c = sigmoid(-g), v = sigmoid(g) * G(z)
__device__ __forceinline__ void gate_cv(float z, float g, float& c, float& v) {
    const float eg  = __expf(g);
    const float inv = frcp(1.0f + eg);
    c = inv;
    const float smg = eg * inv;
    float G;
    if (z >= 0.0f) G = z + 0.5f;
    else {
        const float ez = __expf(z);
        G = ez * frcp(1.0f + ez);
    }
    v = smg * G;
}

// ---------------------------------------------------------------------------
// fp16 HMMA GEMM (NT): C[M,Ntot] = A[M,512] * B[Ntot,512]^T, fp32 accum
// 128x128x64 tile, 8 warps (2Mx4N), 3-stage cp.async, SW128 smem
// ---------------------------------------------------------------------------
#define KK       512
#define NCHG     (KK / 64)          // 8 K-chunks
#define STAGE_B  32768
#define NSTAGE   3
#define SMEM_DYN (NSTAGE * STAGE_B + 1024)

__global__ void __launch_bounds__(256)
gemm_f16_mma(const __half* __restrict__ A,
             const __half* __restrict__ Bw,
             float* __restrict__ C,
             int Ntot)
{
    extern __shared__ char dyn_smem[];
    const uint32_t smem_al = (smem_u32(dyn_smem) + 1023u) & ~1023u;

    const int tid  = threadIdx.x;
    const int lane = tid & 31;
    const int wid  = tid >> 5;
    const int wm   = wid & 1;
    const int wn   = wid >> 1;

    const int m0 = blockIdx.y * 128;
    const int n0 = blockIdx.x * 128;

    const char* Ab = (const char*)(A  + (size_t)m0 * KK);
    const char* Bb = (const char*)(Bw + (size_t)n0 * KK);

    const uint32_t aBase = (uint32_t)((wm * 64 + ((lane >> 3) & 1) * 8 + (lane & 7)) * 128
                                      + (lane >> 4) * 16);
    const uint32_t bBase = (uint32_t)((wn * 32 + (lane >> 4) * 8 + (lane & 7)) * 128
                                      + ((lane >> 3) & 1) * 16);

    float acc[4][4][4];
#pragma unroll
    for (int i = 0; i < 4; ++i)
#pragma unroll
        for (int j = 0; j < 4; ++j)
#pragma unroll
            for (int k = 0; k < 4; ++k) acc[i][j][k] = 0.0f;

    auto load_stage = [&](int i) {
        const uint32_t base = smem_al + (i % NSTAGE) * STAGE_B;
        const size_t kofs = (size_t)i * 128;  // bytes into K row (64 halves)
#pragma unroll
        for (int p = 0; p < 8; ++p) {
            const int idx = tid + p * 256;
            const int r = (idx >> 3) & 127;
            const int c = idx & 7;
            const uint32_t so = swz((uint32_t)(r << 7) + (uint32_t)(c << 4));
            if (idx < 1024)
                cp_async16(base + so,         Ab + (size_t)r * (KK * 2) + kofs + c * 16);
            else
                cp_async16(base + 16384 + so, Bb + (size_t)r * (KK * 2) + kofs + c * 16);
        }
        asm volatile("cp.async.commit_group;" ::: "memory");
    };

    load_stage(0);
    load_stage(1);

    for (int i = 0; i < NCHG; ++i) {
        if (i + 1 < NCHG) asm volatile("cp.async.wait_group 1;" ::: "memory");
        else              asm volatile("cp.async.wait_group 0;" ::: "memory");
        __syncthreads();
        if (i + 2 < NCHG) load_stage(i + 2);

        const uint32_t sA = smem_al + (i % NSTAGE) * STAGE_B;
        const uint32_t sB = sA + 16384;

#pragma unroll
        for (int ks = 0; ks < 4; ++ks) {
            uint32_t afr[4][4], bfr[2][4];
#pragma unroll
            for (int mt = 0; mt < 4; ++mt)
                ldsm4(afr[mt], sA + swz(aBase + (uint32_t)(mt * 2048 + ks * 32)));
#pragma unroll
            for (int q = 0; q < 2; ++q)
                ldsm4(bfr[q], sB + swz(bBase + (uint32_t)(q * 2048 + ks * 32)));
#pragma unroll
            for (int mt = 0; mt < 4; ++mt)
#pragma unroll
                for (int nt = 0; nt < 4; ++nt) {
                    uint32_t b2[2] = { bfr[nt >> 1][(nt & 1) * 2 + 0],
                                       bfr[nt >> 1][(nt & 1) * 2 + 1] };
                    mma16816(acc[mt][nt], afr[mt], b2);
                }
        }
        __syncthreads();
    }

    const int er = lane >> 2;
    const int ec = (lane & 3) * 2;
#pragma unroll
    for (int mt = 0; mt < 4; ++mt) {
#pragma unroll
        for (int nt = 0; nt < 4; ++nt) {
            float* p0 = C + (size_t)(m0 + wm * 64 + mt * 16 + er) * Ntot
                          + n0 + wn * 32 + nt * 8 + ec;
            float* p1 = p0 + (size_t)8 * Ntot;
            *reinterpret_cast<float2*>(p0) = make_float2(acc[mt][nt][0], acc[mt][nt][1]);
            *reinterpret_cast<float2*>(p1) = make_float2(acc[mt][nt][2], acc[mt][nt][3]);
        }
    }
}

// ---------------------------------------------------------------------------
// fp32 -> fp16 cast (vectorized, n % 4 == 0)
// ---------------------------------------------------------------------------
__global__ void __launch_bounds__(256)
f32_to_f16(const float* __restrict__ in, __half* __restrict__ out, size_t n4)
{
    for (size_t i = (size_t)blockIdx.x * blockDim.x + threadIdx.x; i < n4;
         i += (size_t)gridDim.x * blockDim.x) {
        const float4 v = reinterpret_cast<const float4*>(in)[i];
        __half2 h0 = __floats2half2_rn(v.x, v.y);
        __half2 h1 = __floats2half2_rn(v.z, v.w);
        reinterpret_cast<__half2*>(out)[i * 2 + 0] = h0;
        reinterpret_cast<__half2*>(out)[i * 2 + 1] = h1;
    }
}

// ---------------------------------------------------------------------------
// Scan pass 1: per (b, chunk, h): A = prod c, B = local scan from 0
// ---------------------------------------------------------------------------
__global__ void __launch_bounds__(256)
scan_pass1(const float* __restrict__ hg,
           float* __restrict__ chA, float* __restrict__ chB)
{
    const int idx = blockIdx.x * blockDim.x + threadIdx.x;
    const int hh = idx & 511;
    const int bc = idx >> 9;
    const int b  = bc >> 5;
    const int ck = bc & (NCHK - 1);

    const float* base = hg + ((size_t)b * SS + (size_t)ck * CLEN) * 1024;

    float A = 1.0f, h = 0.0f;
    constexpr int U = 8;
#pragma unroll 1
    for (int s = 0; s < CLEN; s += U) {
        float z[U], g[U];
#pragma unroll
        for (int u = 0; u < U; ++u) {
            const size_t off = (size_t)(s + u) * 1024;
            z[u] = base[off + hh];
            g[u] = base[off + 512 + hh];
        }
#pragma unroll
        for (int u = 0; u < U; ++u) {
            float c, v;
            gate_cv(z[u], g[u], c, v);
            h = fmaf(c, h, v);
            A *= c;
        }
    }
    chA[idx] = A;
    chB[idx] = h;
}

// ---------------------------------------------------------------------------
// Scan pass 2: per (b, h) combine chunk summaries -> h_start + h_n
// ---------------------------------------------------------------------------
__global__ void __launch_bounds__(256)
scan_pass2(const float* __restrict__ chA, const float* __restrict__ chB,
           float* __restrict__ hstart, float* __restrict__ hn_out)
{
    const int idx = blockIdx.x * blockDim.x + threadIdx.x;
    const int hh = idx & 511;
    const int b  = idx >> 9;

    float h = 0.0f;
#pragma unroll
    for (int ck = 0; ck < NCHK; ++ck) {
        const int cidx = (b * NCHK + ck) * 512 + hh;
        hstart[cidx] = h;
        h = fmaf(chA[cidx], h, chB[cidx]);
    }
    hn_out[idx] = h;
}

// ---------------------------------------------------------------------------
// Scan pass 3: replay each chunk from exact h_start, write fp16 h
// ---------------------------------------------------------------------------
__global__ void __launch_bounds__(256)
scan_pass3(const float* __restrict__ hg, const float* __restrict__ hstart,
           __half* __restrict__ hout)
{
    const int idx = blockIdx.x * blockDim.x + threadIdx.x;
    const int hh = idx & 511;
    const int bc = idx >> 9;
    const int b  = bc >> 5;
    const int ck = bc & (NCHK - 1);

    const float* base = hg + ((size_t)b * SS + (size_t)ck * CLEN) * 1024;
    __half* hb = hout + ((size_t)b * SS + (size_t)ck * CLEN) * HH;

    float h = hstart[idx];
    constexpr int U = 8;
#pragma unroll 1
    for (int s = 0; s < CLEN; s += U) {
        float z[U], g[U];
#pragma unroll
        for (int u = 0; u < U; ++u) {
            const size_t off = (size_t)(s + u) * 1024;
            z[u] = base[off + hh];
            g[u] = base[off + 512 + hh];
        }
#pragma unroll
        for (int u = 0; u < U; ++u) {
            float c, v;
            gate_cv(z[u], g[u], c, v);
            h = fmaf(c, h, v);
            hb[(size_t)(s + u) * HH + hh] = __float2half(h);
        }
    }
}

// ---------------------------------------------------------------------------
// Launch
// ---------------------------------------------------------------------------
extern "C" void kernel_launch(void* const* d_in, const int* in_sizes, int n_in,
                              void* d_out, int out_size)
{
    const float* x     = (const float*)d_in[0];
    const float* W_hg  = (const float*)d_in[2];
    const float* W_out = (const float*)d_in[3];
    float* out = (float*)d_out;

    float *hg_ptr, *chA, *chB, *hstart;
    __half *xh, *hh_ptr, *w1h, *w2h;
    cudaGetSymbolAddress((void**)&hg_ptr, g_hg);
    cudaGetSymbolAddress((void**)&xh, g_xh);
    cudaGetSymbolAddress((void**)&hh_ptr, g_hh);
    cudaGetSymbolAddress((void**)&w1h, g_w1h);
    cudaGetSymbolAddress((void**)&w2h, g_w2h);
    cudaGetSymbolAddress((void**)&chA, g_chA);
    cudaGetSymbolAddress((void**)&chB, g_chB);
    cudaGetSymbolAddress((void**)&hstart, g_hstart);
    float* hn = out + (size_t)M_TOT * OO;

    cudaFuncSetAttribute(gemm_f16_mma, cudaFuncAttributeMaxDynamicSharedMemorySize, SMEM_DYN);

    // fp16 casts
    f32_to_f16<<<2048, 256>>>(x, xh, (size_t)M_TOT * DD / 4);
    f32_to_f16<<<128, 256>>>(W_hg, w1h, (size_t)1024 * DD / 4);
    f32_to_f16<<<128, 256>>>(W_out, w2h, (size_t)512 * HH / 4);

    // GEMM1: hg = x @ W_hg^T  (M=65536, N=1024, K=512)
    {
        dim3 grid(1024 / 128, M_TOT / 128);
        gemm_f16_mma<<<grid, 256, SMEM_DYN>>>(xh, w1h, hg_ptr, 1024);
    }

    // Parallel scan
    scan_pass1<<<NCC / 256, 256>>>(hg_ptr, chA, chB);
    scan_pass2<<<NCHAN / 256, 256>>>(chA, chB, hstart, hn);
    scan_pass3<<<NCC / 256, 256>>>(hg_ptr, hstart, hh_ptr);

    // GEMM2: out = h @ W_out^T  (M=65536, N=512, K=512)
    {
        dim3 grid(512 / 128, M_TOT / 128);
        gemm_f16_mma<<<grid, 256, SMEM_DYN>>>(hh_ptr, w2h, out, 512);
    }
}